// round 6
// baseline (speedup 1.0000x reference)
#include <cuda_runtime.h>
#include <cuda_bf16.h>
#include <mma.h>
#include <stdint.h>
#include <math.h>

using namespace nvcuda;

#define NN 8192
#define EE 262144
#define DI 256
#define DL 128

#define H_OFF (NN*DL)
#define LOSS_OFF (NN*DL + NN*DI)

// ------------------------- scratch (__device__ globals; zero-initialized) -------------------------
__device__ float g_xl_e[NN*DL];
__device__ float g_xr_e[NN*DL];
__device__ float g_xl_p[NN*DL];
__device__ float g_xr_p[NN*DL];
__device__ float g_xl_d[NN*DI];
__device__ float g_xr_d[NN*DI];
__device__ float g_g1[NN*DL];
__device__ float g_g2[NN*DL];
__device__ __nv_bfloat16 g_q16[NN*DL];
__device__ __nv_bfloat16 g_p16[NN*DL];
__device__ __nv_bfloat16 g_n16[NN*DL];
__device__ int g_perm[NN];
__device__ int g_ptmp[NN];
__device__ unsigned g_bits0[NN];
__device__ unsigned g_bits1[NN];
__device__ float g_bns[3][DL];
__device__ float g_bnq[3][DL];
__device__ float g_acc[2];         // [0]=rec_sum [1]=ctr_sum
__device__ unsigned g_cnt;

// bf16 split buffers
__device__ __nv_bfloat16 g_Ah[NN*DI];
__device__ __nv_bfloat16 g_Al[NN*DI];
__device__ __nv_bfloat16 g_Bh[DI*512];
__device__ __nv_bfloat16 g_Bl[DI*512];

// CSR scratch (per graph)
__device__ int g_deg_s[NN];
__device__ int g_deg_f[NN];
__device__ int g_cur_s[NN];
__device__ int g_cur_f[NN];
__device__ int g_rp_s[NN+1];
__device__ int g_src_s[EE];
__device__ float g_w_s[EE];
__device__ int g_rp_f[NN+1];
__device__ int g_src_f[EE];
__device__ float g_w_f[EE];

// ------------------------- threefry2x32-20 -------------------------
__device__ __forceinline__ void tfry(uint32_t k0, uint32_t k1, uint32_t x0, uint32_t x1,
                                     uint32_t* o0, uint32_t* o1) {
    uint32_t ks2 = k0 ^ k1 ^ 0x1BD11BDAu;
    x0 += k0; x1 += k1;
#define RR(r) { x0 += x1; x1 = (x1 << (r)) | (x1 >> (32 - (r))); x1 ^= x0; }
    RR(13) RR(15) RR(26) RR(6)  x0 += k1;  x1 += ks2 + 1u;
    RR(17) RR(29) RR(16) RR(24) x0 += ks2; x1 += k0 + 2u;
    RR(13) RR(15) RR(26) RR(6)  x0 += k0;  x1 += k1 + 3u;
    RR(17) RR(29) RR(16) RR(24) x0 += k1;  x1 += ks2 + 4u;
    RR(13) RR(15) RR(26) RR(6)  x0 += ks2; x1 += k0 + 5u;
#undef RR
    *o0 = x0; *o1 = x1;
}

// keys[0:2]=sub1, [2:4]=sub2, [4:6]=k2  (pure function of key(42))
__device__ __forceinline__ void all_keys(uint32_t* ks) {
    uint32_t a0, a1, b0, b1;
    tfry(0u, 42u, 0u, 2u, &a0, &a1);
    tfry(0u, 42u, 1u, 3u, &b0, &b1);
    uint32_t k1_0 = a0, k1_1 = b0;
    uint32_t c0, c1, d0, d1;
    tfry(k1_0, k1_1, 0u, 2u, &c0, &c1);
    tfry(k1_0, k1_1, 1u, 3u, &d0, &d1);
    ks[0] = c1; ks[1] = d1;
    uint32_t e0, e1, f0, f1;
    tfry(c0, d0, 0u, 2u, &e0, &e1);
    tfry(c0, d0, 1u, 3u, &f0, &f1);
    ks[2] = e1; ks[3] = f1;
    ks[4] = a1; ks[5] = b1;
}

// ------------------------- role bodies -------------------------
__device__ void cvt4_body(int lb, const float* __restrict__ src,
                          __nv_bfloat16* __restrict__ hi, __nv_bfloat16* __restrict__ lo, int n4) {
    int i = lb * 256 + threadIdx.x;
    if (i >= n4) return;
    float4 a = ((const float4*)src)[i];
    __nv_bfloat162 h0 = __floats2bfloat162_rn(a.x, a.y);
    __nv_bfloat162 h1 = __floats2bfloat162_rn(a.z, a.w);
    float lx = a.x - __bfloat162float(__low2bfloat16(h0));
    float ly = a.y - __bfloat162float(__high2bfloat16(h0));
    float lz = a.z - __bfloat162float(__low2bfloat16(h1));
    float lw = a.w - __bfloat162float(__high2bfloat16(h1));
    ((__nv_bfloat162*)hi)[i * 2] = h0;
    ((__nv_bfloat162*)hi)[i * 2 + 1] = h1;
    ((__nv_bfloat162*)lo)[i * 2] = __floats2bfloat162_rn(lx, ly);
    ((__nv_bfloat162*)lo)[i * 2 + 1] = __floats2bfloat162_rn(lz, lw);
}

__device__ void bits_body(int lb, int which, unsigned* __restrict__ bits) {
    int i = lb * 256 + threadIdx.x;
    if (i >= NN / 2) return;
    uint32_t ks[6];
    all_keys(ks);
    uint32_t lo, hi;
    tfry(ks[which * 2], ks[which * 2 + 1], (uint32_t)i, (uint32_t)(i + NN / 2), &lo, &hi);
    bits[i] = lo; bits[i + NN / 2] = hi;
}

__device__ void hist_body(int lb, const int* __restrict__ dst, int* __restrict__ deg) {
    int e = lb * 256 + threadIdx.x;
    if (e < EE) atomicAdd(&deg[dst[e]], 1);
}

// warp per element; NT = threads per block
template<int NT>
__device__ void rank_body(int lb, const unsigned* __restrict__ bits,
                          const int* __restrict__ pin, int* __restrict__ pout, int use_identity) {
    int gt = lb * NT + threadIdx.x;
    int i = gt >> 5, lane = threadIdx.x & 31;
    if (i >= NN) return;
    unsigned long long ki = (((unsigned long long)bits[i]) << 13) | (unsigned)i;
    int rank = 0;
    for (int j = lane; j < NN; j += 32) {
        unsigned long long kj = (((unsigned long long)bits[j]) << 13) | (unsigned)j;
        rank += (kj < ki);
    }
#pragma unroll
    for (int o = 16; o; o >>= 1) rank += __shfl_down_sync(0xffffffffu, rank, o);
    if (lane == 0) pout[rank] = use_identity ? i : pin[i];
}

// exclusive scan over NN ints; one block of 1024 threads
__device__ void scan_body(const int* __restrict__ deg, int* __restrict__ rp, int* __restrict__ cur) {
    __shared__ int wsum[32];
    int tid = threadIdx.x;
    int lane = tid & 31, w = tid >> 5;
    int loc[8]; int s = 0;
#pragma unroll
    for (int i = 0; i < 8; i++) { loc[i] = deg[tid * 8 + i]; s += loc[i]; }
    int ss = s;
#pragma unroll
    for (int o = 1; o < 32; o <<= 1) { int v = __shfl_up_sync(0xffffffffu, ss, o); if (lane >= o) ss += v; }
    if (lane == 31) wsum[w] = ss;
    __syncthreads();
    if (w == 0) {
        int v = wsum[lane];
#pragma unroll
        for (int o = 1; o < 32; o <<= 1) { int u = __shfl_up_sync(0xffffffffu, v, o); if (lane >= o) v += u; }
        wsum[lane] = v;
    }
    __syncthreads();
    int base = ss - s + (w > 0 ? wsum[w - 1] : 0);
#pragma unroll
    for (int i = 0; i < 8; i++) { rp[tid * 8 + i] = base; cur[tid * 8 + i] = base; base += loc[i]; }
    if (tid == 1023) rp[NN] = base;
}

__device__ void fill_body(int lb, const int* __restrict__ src, const int* __restrict__ dst,
                          const float* __restrict__ w, int* __restrict__ cur,
                          int* __restrict__ srcS, float* __restrict__ wS) {
    int e = lb * 256 + threadIdx.x;
    if (e >= EE) return;
    int d = dst[e];
    int pos = atomicAdd(&cur[d], 1);
    srcS[pos] = src[e];
    wS[pos] = w[e];
}

__device__ __forceinline__ float keep_val(int k) {
    uint32_t ks[6];
    all_keys(ks);
    uint32_t lo, hi;
    int i = (k < 128) ? k : (k - 128);
    tfry(ks[4], ks[5], (uint32_t)i, (uint32_t)(i + 128), &lo, &hi);
    uint32_t u = (k < 128) ? lo : hi;
    float uf = __uint_as_float((u >> 9) | 0x3f800000u) - 1.0f;
    return (uf >= 0.3f) ? 1.f : 0.f;
}

// enc B pack (NT threads): [256][512] = [Wl | Wr | keep*Wl | keep*Wr]
template<int NT>
__device__ void packB_enc_body(int lb, const float* __restrict__ Wl, const float* __restrict__ Wr) {
    int idx = lb * NT + threadIdx.x;
    if (idx >= DI * 512) return;
    int k = idx >> 9, c = idx & 511;
    float v;
    if (c < 128) v = Wl[k * 128 + c];
    else if (c < 256) v = Wr[k * 128 + c - 128];
    else if (c < 384) v = keep_val(k) * Wl[k * 128 + c - 256];
    else v = keep_val(k) * Wr[k * 128 + c - 384];
    __nv_bfloat16 h = __float2bfloat16_rn(v);
    g_Bh[idx] = h;
    g_Bl[idx] = __float2bfloat16_rn(v - __bfloat162float(h));
}

__device__ void packB_dec_body(int lb, const float* __restrict__ Wl, const float* __restrict__ Wr) {
    int idx = lb * 256 + threadIdx.x;
    if (idx >= DL * 512) return;
    int k = idx >> 9, c = idx & 511;
    float v = (c < 256) ? Wl[k * 256 + c] : Wr[k * 256 + c - 256];
    __nv_bfloat16 h = __float2bfloat16_rn(v);
    g_Bh[idx] = h;
    g_Bl[idx] = __float2bfloat16_rn(v - __bfloat162float(h));
}

// bf16x3 GEMM body: C[M,512] = A[M,K] @ B[K,512]; block linear index bx in [0,512)
__device__ void gemm3_body(int bx, const __nv_bfloat16* __restrict__ Ah,
                           const __nv_bfloat16* __restrict__ Al, int K,
                           float* o0, float* o1, float* o2, float* o3, int lgw) {
    __shared__ __nv_bfloat16 sAh[64 * 40], sAl[64 * 40];
    __shared__ __nv_bfloat16 sBh[32 * 136], sBl[32 * 136];
    int tid = threadIdx.x;
    int warp = tid >> 5;
    int wm = warp >> 2, wn = warp & 3;
    int row0 = (bx >> 2) * 64, col0 = (bx & 3) * 128;
    wmma::fragment<wmma::accumulator, 16, 16, 16, float> c[2][2];
#pragma unroll
    for (int i = 0; i < 2; i++)
#pragma unroll
        for (int j = 0; j < 2; j++) wmma::fill_fragment(c[i][j], 0.f);
    int r = tid >> 2, q = tid & 3;
    for (int kp = 0; kp < K; kp += 32) {
        __syncthreads();
        *(uint4*)&sAh[r * 40 + q * 8] = *(const uint4*)&Ah[(row0 + r) * K + kp + q * 8];
        *(uint4*)&sAl[r * 40 + q * 8] = *(const uint4*)&Al[(row0 + r) * K + kp + q * 8];
#pragma unroll
        for (int v = 0; v < 2; v++) {
            int idx = tid + v * 256;
            int k = idx >> 4, nq = idx & 15;
            *(uint4*)&sBh[k * 136 + nq * 8] = *(const uint4*)&g_Bh[(kp + k) * 512 + col0 + nq * 8];
            *(uint4*)&sBl[k * 136 + nq * 8] = *(const uint4*)&g_Bl[(kp + k) * 512 + col0 + nq * 8];
        }
        __syncthreads();
#pragma unroll
        for (int ks = 0; ks < 32; ks += 16) {
            wmma::fragment<wmma::matrix_a, 16, 16, 16, __nv_bfloat16, wmma::row_major> ah[2], al[2];
            wmma::fragment<wmma::matrix_b, 16, 16, 16, __nv_bfloat16, wmma::row_major> bh[2], bl[2];
#pragma unroll
            for (int i = 0; i < 2; i++) {
                wmma::load_matrix_sync(ah[i], &sAh[(wm * 32 + i * 16) * 40 + ks], 40);
                wmma::load_matrix_sync(al[i], &sAl[(wm * 32 + i * 16) * 40 + ks], 40);
            }
#pragma unroll
            for (int j = 0; j < 2; j++) {
                wmma::load_matrix_sync(bh[j], &sBh[ks * 136 + wn * 32 + j * 16], 136);
                wmma::load_matrix_sync(bl[j], &sBl[ks * 136 + wn * 32 + j * 16], 136);
            }
#pragma unroll
            for (int i = 0; i < 2; i++)
#pragma unroll
                for (int j = 0; j < 2; j++) {
                    wmma::mma_sync(c[i][j], ah[i], bh[j], c[i][j]);
                    wmma::mma_sync(c[i][j], ah[i], bl[j], c[i][j]);
                    wmma::mma_sync(c[i][j], al[i], bh[j], c[i][j]);
                }
        }
    }
    float* ob[4] = {o0, o1, o2, o3};
    int W = 1 << lgw, msk = W - 1;
#pragma unroll
    for (int i = 0; i < 2; i++)
#pragma unroll
        for (int j = 0; j < 2; j++) {
            int colg = col0 + wn * 32 + j * 16;
            float* dst = ob[colg >> lgw] + (size_t)(row0 + wm * 32 + i * 16) * W + (colg & msk);
            wmma::store_matrix_sync(dst, c[i][j], W, wmma::mem_row_major);
        }
}

// fused single-pass GAT: warp per node; optional perm indirection (x_n = x[perm])
template<int D, bool P>
__device__ void gat_body(int lb, const int* __restrict__ rp, const int* __restrict__ srcS,
                         const float* __restrict__ wS,
                         const float* __restrict__ xl, const float* __restrict__ xr,
                         const float* __restrict__ att,
                         const float* __restrict__ bias, float* __restrict__ out,
                         const int* __restrict__ pidx) {
    constexpr int T = D / 128;
    int node = (lb * 256 + threadIdx.x) >> 5;
    int lane = threadIdx.x & 31;
    if (node >= NN) return;
    int beg = rp[node], end = rp[node + 1];
    int nr = P ? pidx[node] : node;
    const float4* xrp = (const float4*)(xr + nr * D);
    const float4* ap = (const float4*)att;
    float4 xrv[T], av[T], acc[T];
#pragma unroll
    for (int t = 0; t < T; t++) {
        xrv[t] = xrp[lane + t * 32];
        av[t] = ap[lane + t * 32];
        acc[t] = make_float4(0.f, 0.f, 0.f, 0.f);
    }
    float den = 0.f;
    for (int k = beg; k < end; k++) {
        int s = srcS[k];
        if (P) s = pidx[s];
        const float4* xp = (const float4*)(xl + s * D);
        float4 v[T];
        float lg = 0.f;
#pragma unroll
        for (int t = 0; t < T; t++) {
            v[t] = xp[lane + t * 32];
            float ex = v[t].x + xrv[t].x; ex = ex > 0.f ? ex : 0.2f * ex;
            float ey = v[t].y + xrv[t].y; ey = ey > 0.f ? ey : 0.2f * ey;
            float ez = v[t].z + xrv[t].z; ez = ez > 0.f ? ez : 0.2f * ez;
            float ew = v[t].w + xrv[t].w; ew = ew > 0.f ? ew : 0.2f * ew;
            lg += ex * av[t].x + ey * av[t].y + ez * av[t].z + ew * av[t].w;
        }
#pragma unroll
        for (int o = 16; o; o >>= 1) lg += __shfl_xor_sync(0xffffffffu, lg, o);
        float w = expf(lg);
        den += w;
        float a = w * wS[k];
#pragma unroll
        for (int t = 0; t < T; t++) {
            acc[t].x += a * v[t].x; acc[t].y += a * v[t].y;
            acc[t].z += a * v[t].z; acc[t].w += a * v[t].w;
        }
    }
    float inv = 1.f / (den + 1e-16f);
    float4* op = (float4*)(out + node * D);
    const float4* bp = (const float4*)bias;
#pragma unroll
    for (int t = 0; t < T; t++) {
        float4 b = bp[lane + t * 32];
        op[lane + t * 32] = make_float4(acc[t].x * inv + b.x, acc[t].y * inv + b.y,
                                        acc[t].z * inv + b.z, acc[t].w * inv + b.w);
    }
}

__device__ void bnstats_body(int lb, const float* __restrict__ a0, const float* __restrict__ a1,
                             const float* __restrict__ a2) {
    int y = lb / 32, xb = lb % 32;
    const float* A = (y == 0) ? a0 : (y == 1 ? a1 : a2);
    int c = threadIdx.x % DL;
    int part = threadIdx.x / DL;
    int rbase = xb * 256 + part * 128;
    float s = 0.f, q = 0.f;
    for (int r = 0; r < 128; r++) {
        float v = A[(rbase + r) * DL + c];
        s += v; q += v * v;
    }
    atomicAdd(&g_bns[y][c], s);
    atomicAdd(&g_bnq[y][c], q);
}

__device__ void bnl2_body(int lb, const float* __restrict__ a0, const float* __restrict__ a1,
                          const float* __restrict__ a2,
                          const float* __restrict__ gamma, const float* __restrict__ beta) {
    int y = lb / 1024, xb = lb % 1024;
    const float* A = (y == 0) ? a0 : (y == 1 ? a1 : a2);
    __nv_bfloat16* B = (y == 0) ? g_q16 : (y == 1 ? g_p16 : g_n16);
    int gt = xb * 256 + threadIdx.x;
    int row = gt >> 5, lane = threadIdx.x & 31;
    if (row >= NN) return;
    float4 v = ((const float4*)(A + row * DL))[lane];
    float4 sm = ((const float4*)g_bns[y])[lane];
    float4 sq = ((const float4*)g_bnq[y])[lane];
    float4 ga = ((const float4*)gamma)[lane];
    float4 be = ((const float4*)beta)[lane];
    float mu, var, t;
#define BNE(comp) \
    mu = sm.comp * (1.f / NN); var = sq.comp * (1.f / NN) - mu * mu; \
    t = (v.comp - mu) * rsqrtf(var + 1e-5f) * ga.comp + be.comp; \
    v.comp = t > 0.f ? t : expm1f(t);
    BNE(x) BNE(y) BNE(z) BNE(w)
#undef BNE
    float s = v.x * v.x + v.y * v.y + v.z * v.z + v.w * v.w;
#pragma unroll
    for (int o = 16; o; o >>= 1) s += __shfl_xor_sync(0xffffffffu, s, o);
    float inv = 1.f / sqrtf(s);
    __nv_bfloat162* qp = (__nv_bfloat162*)(B + row * DL);
    qp[lane * 2]     = __floats2bfloat162_rn(v.x * inv, v.y * inv);
    qp[lane * 2 + 1] = __floats2bfloat162_rn(v.z * inv, v.w * inv);
}

// ------------------------- InfoNCE on tensor cores (bf16 wmma) -------------------------
#define NCE_SMEM (64*128*2 + 128*128*2 + 8*16*68*4)
__device__ void nce_body(int bx) {
    extern __shared__ char smraw[];
    __nv_bfloat16* qs = (__nv_bfloat16*)smraw;            // [64][128]
    __nv_bfloat16* ns = qs + 64 * 128;                    // [128][128]
    float* stb = (float*)(ns + 128 * 128);                // 8 warps x [16][68]
    __shared__ float pos2[64];
    __shared__ float rowS[64];
    __shared__ float blksum;
    int tid = threadIdx.x;
    int warp = tid >> 5, lane = tid & 31;
    int r0 = bx * 64;

    {
        const uint4* src = (const uint4*)(g_q16 + r0 * DL);
        uint4* dst4 = (uint4*)qs;
#pragma unroll
        for (int i = tid; i < 64 * 128 / 8; i += 256) dst4[i] = src[i];
    }
    if (tid < 64) rowS[tid] = 0.f;
    if (tid == 0) blksum = 0.f;
    __syncthreads();

    {
        int row = tid >> 2, part = tid & 3;
        float s = 0.f;
        const __nv_bfloat16* pr = g_p16 + (r0 + row) * DL;
        for (int k = part * 32; k < part * 32 + 32; k++)
            s += __bfloat162float(qs[row * 128 + k]) * __bfloat162float(pr[k]);
        s += __shfl_down_sync(0xffffffffu, s, 1);
        s += __shfl_down_sync(0xffffffffu, s, 2);
        if (part == 0) pos2[row] = 2.f * s;
    }

    int wm = (warp & 3) * 16;
    int wn = (warp >> 2) * 64;
    float* myst = stb + warp * (16 * 68);
    int lrow = lane >> 1;
    int lcol0 = (lane & 1) * 32;
    float sacc = 0.f;

    wmma::fragment<wmma::accumulator, 16, 16, 16, float> c[4];
    for (int n0 = 0; n0 < NN; n0 += 128) {
        __syncthreads();
        {
            const uint4* src = (const uint4*)(g_n16 + n0 * DL);
            uint4* dst4 = (uint4*)ns;
#pragma unroll
            for (int i = tid; i < 128 * 128 / 8; i += 256) dst4[i] = src[i];
        }
        __syncthreads();
#pragma unroll
        for (int j = 0; j < 4; j++) wmma::fill_fragment(c[j], 0.f);
#pragma unroll
        for (int k0 = 0; k0 < 8; k0++) {
            wmma::fragment<wmma::matrix_a, 16, 16, 16, __nv_bfloat16, wmma::row_major> a;
            wmma::load_matrix_sync(a, qs + wm * 128 + k0 * 16, 128);
#pragma unroll
            for (int j = 0; j < 4; j++) {
                wmma::fragment<wmma::matrix_b, 16, 16, 16, __nv_bfloat16, wmma::col_major> b;
                wmma::load_matrix_sync(b, ns + (wn + j * 16) * 128 + k0 * 16, 128);
                wmma::mma_sync(c[j], a, b, c[j]);
            }
        }
#pragma unroll
        for (int j = 0; j < 4; j++)
            wmma::store_matrix_sync(myst + j * 16, c[j], 68, wmma::mem_row_major);
        __syncwarp();
#pragma unroll
        for (int cc = 0; cc < 32; cc++) {
            float v = myst[lrow * 68 + lcol0 + cc];
            sacc += __expf(2.f * v);
        }
        __syncwarp();
    }
    sacc += __shfl_xor_sync(0xffffffffu, sacc, 1);
    if ((lane & 1) == 0) atomicAdd(&rowS[wm + lrow], sacc);
    __syncthreads();
    if (tid < 64) {
        float S = rowS[tid];
        float p = pos2[tid];
        float l = logf(S + __expf(p)) - p;
        atomicAdd(&blksum, l);
    }
    __syncthreads();
    if (tid == 0) atomicAdd(&g_acc[1], blksum);
}

// ------------------------- merged kernels -------------------------
// kA: cvt_enc(2048) | bits0(16) | bits1(16) | hist_s(1024) | hist_f(1024)
__global__ void __launch_bounds__(256) kA(const float* x, const int* s_dst, const int* f_dst) {
    int b = blockIdx.x;
    if (b < 2048) cvt4_body(b, x, g_Ah, g_Al, NN * DI / 4);
    else if (b < 2064) bits_body(b - 2048, 0, g_bits0);
    else if (b < 2080) bits_body(b - 2064, 1, g_bits1);
    else if (b < 3104) hist_body(b - 2080, s_dst, g_deg_s);
    else hist_body(b - 3104, f_dst, g_deg_f);
}

// kB (1024 thr): rank1(256) | scan(2) | packB_enc(128)
__global__ void __launch_bounds__(1024) kB(const float* enc_Wl, const float* enc_Wr) {
    int b = blockIdx.x;
    if (b < 256) rank_body<1024>(b, g_bits0, nullptr, g_ptmp, 1);
    else if (b == 256) scan_body(g_deg_s, g_rp_s, g_cur_s);
    else if (b == 257) scan_body(g_deg_f, g_rp_f, g_cur_f);
    else packB_enc_body<1024>(b - 258, enc_Wl, enc_Wr);
}

// kC: gemm_enc(512) | rank2(1024) | fill_s(1024) | fill_f(1024)
__global__ void __launch_bounds__(256) kC(const int* s_src, const int* s_dst, const float* w_h,
                                          const int* f_src, const int* f_dst, const float* w_h_a) {
    int b = blockIdx.x;
    if (b < 512) gemm3_body(b, g_Ah, g_Al, DI, g_xl_e, g_xr_e, g_xl_p, g_xr_p, 7);
    else if (b < 1536) rank_body<256>(b - 512, g_bits1, g_ptmp, g_perm, 0);
    else if (b < 2560) fill_body(b - 1536, s_src, s_dst, w_h, g_cur_s, g_src_s, g_w_s);
    else fill_body(b - 2560, f_src, f_dst, w_h_a, g_cur_f, g_src_f, g_w_f);
}

// kD: 3 encoder GATs (y = b>>10)
__global__ void __launch_bounds__(256) kD(const float* att, const float* bias, float* hi) {
    int b = blockIdx.x;
    int y = b >> 10, lb = b & 1023;
    if (y == 0) gat_body<DL, false>(lb, g_rp_s, g_src_s, g_w_s, g_xl_e, g_xr_e, att, bias, hi, nullptr);
    else if (y == 1) gat_body<DL, false>(lb, g_rp_f, g_src_f, g_w_f, g_xl_p, g_xr_p, att, bias, g_g1, nullptr);
    else gat_body<DL, true>(lb, g_rp_s, g_src_s, g_w_s, g_xl_e, g_xr_e, att, bias, g_g2, g_perm);
}

// kE: cvt_dec(1024) | packB_dec(256) | bnstats(96)
__global__ void __launch_bounds__(256) kE(const float* hiOut, const float* dec_Wl, const float* dec_Wr) {
    int b = blockIdx.x;
    if (b < 1024) cvt4_body(b, hiOut, g_Ah, g_Al, NN * DL / 4);
    else if (b < 1280) packB_dec_body(b - 1024, dec_Wl, dec_Wr);
    else bnstats_body(b - 1280, hiOut, g_g1, g_g2);
}

// kF: gemm_dec(512) | bnl2(3072)
__global__ void __launch_bounds__(256) kF(const float* hiOut, const float* bn_g, const float* bn_b) {
    int b = blockIdx.x;
    if (b < 512) gemm3_body(b, g_Ah, g_Al, DL, g_xl_d, g_xr_d, g_xl_d, g_xr_d, 8);
    else bnl2_body(b - 512, hiOut, g_g1, g_g2, bn_g, bn_b);
}

// kG: nce(128) | gat_dec(1024)
__global__ void __launch_bounds__(256) kG(const float* dec_att, const float* dec_b, float* h) {
    int b = blockIdx.x;
    if (b < 128) nce_body(b);
    else gat_body<DI, false>(b - 128, g_rp_s, g_src_s, g_w_s, g_xl_d, g_xr_d, dec_att, dec_b, h, nullptr);
}

// kH: rec(256) + last-block final + next-replay re-zeroing
__global__ void __launch_bounds__(256) kH(const float* x, const float* h, float* loss) {
    float s = 0.f;
    for (int i = blockIdx.x * blockDim.x + threadIdx.x; i < NN * DI; i += gridDim.x * blockDim.x) {
        float d = x[i] - h[i];
        s += d * d;
    }
#pragma unroll
    for (int o = 16; o; o >>= 1) s += __shfl_down_sync(0xffffffffu, s, o);
    __shared__ float red[8];
    int lane = threadIdx.x & 31, wid = threadIdx.x >> 5;
    if (lane == 0) red[wid] = s;
    __syncthreads();
    if (threadIdx.x == 0) {
        float t = 0.f;
        for (int i = 0; i < 8; i++) t += red[i];
        atomicAdd(&g_acc[0], t);
    }
    // re-zero scratch for next graph replay
    int b = blockIdx.x;
    if (threadIdx.x < 32) {
        g_deg_s[b * 32 + threadIdx.x] = 0;
        g_deg_f[b * 32 + threadIdx.x] = 0;
    }
    if (b < 3 && threadIdx.x < DL) { g_bns[b][threadIdx.x] = 0.f; g_bnq[b][threadIdx.x] = 0.f; }
    __threadfence();
    __syncthreads();
    if (threadIdx.x == 0) {
        unsigned old = atomicInc(&g_cnt, 255u);   // wraps to 0 on last block
        if (old == 255u) {
            __threadfence();
            loss[0] = g_acc[0] * (1.f / (float)(NN * DI)) + 0.2f * (g_acc[1] * (1.f / (float)NN));
            g_acc[0] = 0.f; g_acc[1] = 0.f;
        }
    }
}

// ------------------------- host orchestration -------------------------
extern "C" void kernel_launch(void* const* d_in, const int* in_sizes, int n_in,
                              void* d_out, int out_size) {
    (void)in_sizes; (void)n_in; (void)out_size;
    const float* x       = (const float*)d_in[0];
    const int*   gsi     = (const int*)d_in[1];
    const int*   gfi     = (const int*)d_in[2];
    const float* w_h     = (const float*)d_in[3];
    const float* w_h_a   = (const float*)d_in[4];
    const float* enc_Wl  = (const float*)d_in[5];
    const float* enc_Wr  = (const float*)d_in[6];
    const float* enc_att = (const float*)d_in[7];
    const float* enc_b   = (const float*)d_in[8];
    const float* dec_Wl  = (const float*)d_in[9];
    const float* dec_Wr  = (const float*)d_in[10];
    const float* dec_att = (const float*)d_in[11];
    const float* dec_b   = (const float*)d_in[12];
    const float* bn_g    = (const float*)d_in[13];
    const float* bn_b    = (const float*)d_in[14];

    float* out  = (float*)d_out;
    float* hi   = out;
    float* h    = out + H_OFF;
    float* loss = out + LOSS_OFF;

    const int* s_src = gsi;
    const int* s_dst = gsi + EE;
    const int* f_src = gfi;
    const int* f_dst = gfi + EE;

    cudaFuncSetAttribute(kG, cudaFuncAttributeMaxDynamicSharedMemorySize, NCE_SMEM);

    kA<<<4128, 256>>>(x, s_dst, f_dst);
    kB<<<386, 1024>>>(enc_Wl, enc_Wr);
    kC<<<3584, 256>>>(s_src, s_dst, w_h, f_src, f_dst, w_h_a);
    kD<<<3072, 256>>>(enc_att, enc_b, hi);
    kE<<<1376, 256>>>(hi, dec_Wl, dec_Wr);
    kF<<<3584, 256>>>(hi, bn_g, bn_b);
    kG<<<1152, 256, NCE_SMEM>>>(dec_att, dec_b, h);
    kH<<<256, 256>>>(x, h, loss);
}

// round 7
// speedup vs baseline: 1.4284x; 1.4284x over previous
#include <cuda_runtime.h>
#include <cuda_bf16.h>
#include <mma.h>
#include <stdint.h>
#include <math.h>

using namespace nvcuda;

#define NN 8192
#define EE 262144
#define DI 256
#define DL 128

#define H_OFF (NN*DL)
#define LOSS_OFF (NN*DL + NN*DI)

// ------------------------- scratch (__device__ globals; zero-initialized) -------------------------
__device__ float g_xl_e[NN*DL];
__device__ float g_xr_e[NN*DL];
__device__ float g_xl_p[NN*DL];
__device__ float g_xr_p[NN*DL];
__device__ float g_xl_d[NN*DI];
__device__ float g_xr_d[NN*DI];
__device__ float g_g1[NN*DL];
__device__ float g_g2[NN*DL];
__device__ __nv_bfloat16 g_q16[NN*DL];
__device__ __nv_bfloat16 g_p16[NN*DL];
__device__ __nv_bfloat16 g_n16[NN*DL];
__device__ int g_perm[NN];
__device__ int g_ptmp[NN];
__device__ unsigned g_bits0[NN];
__device__ unsigned g_bits1[NN];
__device__ float g_bns[3][DL];
__device__ float g_bnq[3][DL];
__device__ float g_acc[2];         // [0]=rec_sum [1]=ctr_sum
__device__ unsigned g_cnt;

// bf16 split buffers
__device__ __nv_bfloat16 g_Ah[NN*DI];
__device__ __nv_bfloat16 g_Al[NN*DI];
__device__ __nv_bfloat16 g_Bh[DI*512];
__device__ __nv_bfloat16 g_Bl[DI*512];

// CSR scratch (per graph)
__device__ int g_deg_s[NN];
__device__ int g_deg_f[NN];
__device__ int g_cur_s[NN];
__device__ int g_cur_f[NN];
__device__ int g_rp_s[NN+1];
__device__ int g_src_s[EE];
__device__ float g_w_s[EE];
__device__ int g_rp_f[NN+1];
__device__ int g_src_f[EE];
__device__ float g_w_f[EE];

// ------------------------- threefry2x32-20 -------------------------
__device__ __forceinline__ void tfry(uint32_t k0, uint32_t k1, uint32_t x0, uint32_t x1,
                                     uint32_t* o0, uint32_t* o1) {
    uint32_t ks2 = k0 ^ k1 ^ 0x1BD11BDAu;
    x0 += k0; x1 += k1;
#define RR(r) { x0 += x1; x1 = (x1 << (r)) | (x1 >> (32 - (r))); x1 ^= x0; }
    RR(13) RR(15) RR(26) RR(6)  x0 += k1;  x1 += ks2 + 1u;
    RR(17) RR(29) RR(16) RR(24) x0 += ks2; x1 += k0 + 2u;
    RR(13) RR(15) RR(26) RR(6)  x0 += k0;  x1 += k1 + 3u;
    RR(17) RR(29) RR(16) RR(24) x0 += k1;  x1 += ks2 + 4u;
    RR(13) RR(15) RR(26) RR(6)  x0 += ks2; x1 += k0 + 5u;
#undef RR
    *o0 = x0; *o1 = x1;
}

// keys[0:2]=sub1, [2:4]=sub2, [4:6]=k2  (pure function of key(42))
__device__ __forceinline__ void all_keys(uint32_t* ks) {
    uint32_t a0, a1, b0, b1;
    tfry(0u, 42u, 0u, 2u, &a0, &a1);
    tfry(0u, 42u, 1u, 3u, &b0, &b1);
    uint32_t c0, c1, d0, d1;
    tfry(a0, b0, 0u, 2u, &c0, &c1);
    tfry(a0, b0, 1u, 3u, &d0, &d1);
    ks[0] = c1; ks[1] = d1;
    uint32_t e0, e1, f0, f1;
    tfry(c0, d0, 0u, 2u, &e0, &e1);
    tfry(c0, d0, 1u, 3u, &f0, &f1);
    ks[2] = e1; ks[3] = f1;
    ks[4] = a1; ks[5] = b1;
}

// ------------------------- init: zero deg/bn/acc -------------------------
__global__ void __launch_bounds__(256) k_init() {
    int t = blockIdx.x * 256 + threadIdx.x;
    if (t < NN) { g_deg_s[t] = 0; g_deg_f[t] = 0; }
    if (t < DL) {
        g_bns[0][t] = 0.f; g_bns[1][t] = 0.f; g_bns[2][t] = 0.f;
        g_bnq[0][t] = 0.f; g_bnq[1][t] = 0.f; g_bnq[2][t] = 0.f;
    }
    if (t == 0) { g_acc[0] = 0.f; g_acc[1] = 0.f; }
}

// ------------------------- RNG bits (both rounds in one kernel) -------------------------
__global__ void __launch_bounds__(256) k_bits2() {
    int b = blockIdx.x;
    int which = (b < 16) ? 0 : 1;
    int i = (which ? b - 16 : b) * 256 + threadIdx.x;
    if (i >= NN / 2) return;
    uint32_t ks[6];
    all_keys(ks);
    uint32_t lo, hi;
    tfry(ks[which * 2], ks[which * 2 + 1], (uint32_t)i, (uint32_t)(i + NN / 2), &lo, &hi);
    unsigned* bits = which ? g_bits1 : g_bits0;
    bits[i] = lo; bits[i + NN / 2] = hi;
}

// warp per element, lane-strided rank count
__global__ void __launch_bounds__(256) k_rankA() {
    int gt = blockIdx.x * 256 + threadIdx.x;
    int i = gt >> 5, lane = threadIdx.x & 31;
    if (i >= NN) return;
    unsigned long long ki = (((unsigned long long)g_bits0[i]) << 13) | (unsigned)i;
    int rank = 0;
    for (int j = lane; j < NN; j += 32) {
        unsigned long long kj = (((unsigned long long)g_bits0[j]) << 13) | (unsigned)j;
        rank += (kj < ki);
    }
#pragma unroll
    for (int o = 16; o; o >>= 1) rank += __shfl_down_sync(0xffffffffu, rank, o);
    if (lane == 0) g_ptmp[rank] = i;
}

__global__ void __launch_bounds__(256) k_rankB() {
    int gt = blockIdx.x * 256 + threadIdx.x;
    int i = gt >> 5, lane = threadIdx.x & 31;
    if (i >= NN) return;
    unsigned long long ki = (((unsigned long long)g_bits1[i]) << 13) | (unsigned)i;
    int rank = 0;
    for (int j = lane; j < NN; j += 32) {
        unsigned long long kj = (((unsigned long long)g_bits1[j]) << 13) | (unsigned)j;
        rank += (kj < ki);
    }
#pragma unroll
    for (int o = 16; o; o >>= 1) rank += __shfl_down_sync(0xffffffffu, rank, o);
    if (lane == 0) g_perm[rank] = g_ptmp[i];
}

// ------------------------- CSR build -------------------------
__global__ void __launch_bounds__(256) k_hist2(const int* __restrict__ s_dst,
                                               const int* __restrict__ f_dst) {
    int b = blockIdx.x;
    if (b < 1024) {
        int e = b * 256 + threadIdx.x;
        if (e < EE) atomicAdd(&g_deg_s[s_dst[e]], 1);
    } else {
        int e = (b - 1024) * 256 + threadIdx.x;
        if (e < EE) atomicAdd(&g_deg_f[f_dst[e]], 1);
    }
}

__device__ void scan_body(const int* __restrict__ deg, int* __restrict__ rp, int* __restrict__ cur) {
    __shared__ int wsum[32];
    int tid = threadIdx.x;
    int lane = tid & 31, w = tid >> 5;
    int loc[8]; int s = 0;
#pragma unroll
    for (int i = 0; i < 8; i++) { loc[i] = deg[tid * 8 + i]; s += loc[i]; }
    int ss = s;
#pragma unroll
    for (int o = 1; o < 32; o <<= 1) { int v = __shfl_up_sync(0xffffffffu, ss, o); if (lane >= o) ss += v; }
    if (lane == 31) wsum[w] = ss;
    __syncthreads();
    if (w == 0) {
        int v = wsum[lane];
#pragma unroll
        for (int o = 1; o < 32; o <<= 1) { int u = __shfl_up_sync(0xffffffffu, v, o); if (lane >= o) v += u; }
        wsum[lane] = v;
    }
    __syncthreads();
    int base = ss - s + (w > 0 ? wsum[w - 1] : 0);
#pragma unroll
    for (int i = 0; i < 8; i++) { rp[tid * 8 + i] = base; cur[tid * 8 + i] = base; base += loc[i]; }
    if (tid == 1023) rp[NN] = base;
}

__global__ void __launch_bounds__(1024) k_scan2() {
    if (blockIdx.x == 0) scan_body(g_deg_s, g_rp_s, g_cur_s);
    else scan_body(g_deg_f, g_rp_f, g_cur_f);
}

__global__ void __launch_bounds__(256) k_fill2(const int* __restrict__ s_src, const int* __restrict__ s_dst,
                                               const float* __restrict__ w_h,
                                               const int* __restrict__ f_src, const int* __restrict__ f_dst,
                                               const float* __restrict__ w_h_a) {
    int b = blockIdx.x;
    if (b < 1024) {
        int e = b * 256 + threadIdx.x;
        if (e >= EE) return;
        int d = s_dst[e];
        int pos = atomicAdd(&g_cur_s[d], 1);
        g_src_s[pos] = s_src[e];
        g_w_s[pos] = w_h[e];
    } else {
        int e = (b - 1024) * 256 + threadIdx.x;
        if (e >= EE) return;
        int d = f_dst[e];
        int pos = atomicAdd(&g_cur_f[d], 1);
        g_src_f[pos] = f_src[e];
        g_w_f[pos] = w_h_a[e];
    }
}

// ------------------------- cvt / pack bodies -------------------------
__device__ void cvt4_body(int lb, const float* __restrict__ src,
                          __nv_bfloat16* __restrict__ hi, __nv_bfloat16* __restrict__ lo, int n4) {
    int i = lb * 256 + threadIdx.x;
    if (i >= n4) return;
    float4 a = ((const float4*)src)[i];
    __nv_bfloat162 h0 = __floats2bfloat162_rn(a.x, a.y);
    __nv_bfloat162 h1 = __floats2bfloat162_rn(a.z, a.w);
    float lx = a.x - __bfloat162float(__low2bfloat16(h0));
    float ly = a.y - __bfloat162float(__high2bfloat16(h0));
    float lz = a.z - __bfloat162float(__low2bfloat16(h1));
    float lw = a.w - __bfloat162float(__high2bfloat16(h1));
    ((__nv_bfloat162*)hi)[i * 2] = h0;
    ((__nv_bfloat162*)hi)[i * 2 + 1] = h1;
    ((__nv_bfloat162*)lo)[i * 2] = __floats2bfloat162_rn(lx, ly);
    ((__nv_bfloat162*)lo)[i * 2 + 1] = __floats2bfloat162_rn(lz, lw);
}

__device__ __forceinline__ float keep_val(int k) {
    uint32_t ks[6];
    all_keys(ks);
    uint32_t lo, hi;
    int i = (k < 128) ? k : (k - 128);
    tfry(ks[4], ks[5], (uint32_t)i, (uint32_t)(i + 128), &lo, &hi);
    uint32_t u = (k < 128) ? lo : hi;
    float uf = __uint_as_float((u >> 9) | 0x3f800000u) - 1.0f;
    return (uf >= 0.3f) ? 1.f : 0.f;
}

// kCP_enc: cvt_enc(2048) | packB_enc(512)
__global__ void __launch_bounds__(256) kCP_enc(const float* __restrict__ x,
                                               const float* __restrict__ Wl, const float* __restrict__ Wr) {
    int b = blockIdx.x;
    if (b < 2048) { cvt4_body(b, x, g_Ah, g_Al, NN * DI / 4); return; }
    int idx = (b - 2048) * 256 + threadIdx.x;
    if (idx >= DI * 512) return;
    int k = idx >> 9, c = idx & 511;
    float v;
    if (c < 128) v = Wl[k * 128 + c];
    else if (c < 256) v = Wr[k * 128 + c - 128];
    else if (c < 384) v = keep_val(k) * Wl[k * 128 + c - 256];
    else v = keep_val(k) * Wr[k * 128 + c - 384];
    __nv_bfloat16 h = __float2bfloat16_rn(v);
    g_Bh[idx] = h;
    g_Bl[idx] = __float2bfloat16_rn(v - __bfloat162float(h));
}

// bnstats body
__device__ void bnstats_body(int lb, const float* __restrict__ a0, const float* __restrict__ a1,
                             const float* __restrict__ a2) {
    int y = lb / 32, xb = lb % 32;
    const float* A = (y == 0) ? a0 : (y == 1 ? a1 : a2);
    int c = threadIdx.x % DL;
    int part = threadIdx.x / DL;
    int rbase = xb * 256 + part * 128;
    float s = 0.f, q = 0.f;
    for (int r = 0; r < 128; r++) {
        float v = A[(rbase + r) * DL + c];
        s += v; q += v * v;
    }
    atomicAdd(&g_bns[y][c], s);
    atomicAdd(&g_bnq[y][c], q);
}

// kCP_dec: cvt_dec(1024) | packB_dec(256) | bnstats(96)
__global__ void __launch_bounds__(256) kCP_dec(const float* __restrict__ hiOut,
                                               const float* __restrict__ Wl, const float* __restrict__ Wr,
                                               const float* __restrict__ g1, const float* __restrict__ g2) {
    int b = blockIdx.x;
    if (b < 1024) { cvt4_body(b, hiOut, g_Ah, g_Al, NN * DL / 4); return; }
    if (b < 1280) {
        int idx = (b - 1024) * 256 + threadIdx.x;
        if (idx >= DL * 512) return;
        int k = idx >> 9, c = idx & 511;
        float v = (c < 256) ? Wl[k * 256 + c] : Wr[k * 256 + c - 256];
        __nv_bfloat16 h = __float2bfloat16_rn(v);
        g_Bh[idx] = h;
        g_Bl[idx] = __float2bfloat16_rn(v - __bfloat162float(h));
        return;
    }
    bnstats_body(b - 1280, hiOut, g1, g2);
}

// ------------------------- bf16x3 GEMM on tensor cores -------------------------
__global__ void __launch_bounds__(256) k_gemm3(const __nv_bfloat16* __restrict__ Ah,
                                               const __nv_bfloat16* __restrict__ Al, int K,
                                               float* o0, float* o1, float* o2, float* o3, int lgw) {
    __shared__ __nv_bfloat16 sAh[64 * 40], sAl[64 * 40];
    __shared__ __nv_bfloat16 sBh[32 * 136], sBl[32 * 136];
    int tid = threadIdx.x;
    int warp = tid >> 5;
    int wm = warp >> 2, wn = warp & 3;
    int bx = blockIdx.x;
    int row0 = (bx >> 2) * 64, col0 = (bx & 3) * 128;
    wmma::fragment<wmma::accumulator, 16, 16, 16, float> c[2][2];
#pragma unroll
    for (int i = 0; i < 2; i++)
#pragma unroll
        for (int j = 0; j < 2; j++) wmma::fill_fragment(c[i][j], 0.f);
    int r = tid >> 2, q = tid & 3;
    for (int kp = 0; kp < K; kp += 32) {
        __syncthreads();
        *(uint4*)&sAh[r * 40 + q * 8] = *(const uint4*)&Ah[(row0 + r) * K + kp + q * 8];
        *(uint4*)&sAl[r * 40 + q * 8] = *(const uint4*)&Al[(row0 + r) * K + kp + q * 8];
#pragma unroll
        for (int v = 0; v < 2; v++) {
            int idx = tid + v * 256;
            int k = idx >> 4, nq = idx & 15;
            *(uint4*)&sBh[k * 136 + nq * 8] = *(const uint4*)&g_Bh[(kp + k) * 512 + col0 + nq * 8];
            *(uint4*)&sBl[k * 136 + nq * 8] = *(const uint4*)&g_Bl[(kp + k) * 512 + col0 + nq * 8];
        }
        __syncthreads();
#pragma unroll
        for (int ks = 0; ks < 32; ks += 16) {
            wmma::fragment<wmma::matrix_a, 16, 16, 16, __nv_bfloat16, wmma::row_major> ah[2], al[2];
            wmma::fragment<wmma::matrix_b, 16, 16, 16, __nv_bfloat16, wmma::row_major> bh[2], bl[2];
#pragma unroll
            for (int i = 0; i < 2; i++) {
                wmma::load_matrix_sync(ah[i], &sAh[(wm * 32 + i * 16) * 40 + ks], 40);
                wmma::load_matrix_sync(al[i], &sAl[(wm * 32 + i * 16) * 40 + ks], 40);
            }
#pragma unroll
            for (int j = 0; j < 2; j++) {
                wmma::load_matrix_sync(bh[j], &sBh[ks * 136 + wn * 32 + j * 16], 136);
                wmma::load_matrix_sync(bl[j], &sBl[ks * 136 + wn * 32 + j * 16], 136);
            }
#pragma unroll
            for (int i = 0; i < 2; i++)
#pragma unroll
                for (int j = 0; j < 2; j++) {
                    wmma::mma_sync(c[i][j], ah[i], bh[j], c[i][j]);
                    wmma::mma_sync(c[i][j], ah[i], bl[j], c[i][j]);
                    wmma::mma_sync(c[i][j], al[i], bh[j], c[i][j]);
                }
        }
    }
    float* ob[4] = {o0, o1, o2, o3};
    int W = 1 << lgw, msk = W - 1;
#pragma unroll
    for (int i = 0; i < 2; i++)
#pragma unroll
        for (int j = 0; j < 2; j++) {
            int colg = col0 + wn * 32 + j * 16;
            float* dst = ob[colg >> lgw] + (size_t)(row0 + wm * 32 + i * 16) * W + (colg & msk);
            wmma::store_matrix_sync(dst, c[i][j], W, wmma::mem_row_major);
        }
}

// ------------------------- fused single-pass GAT (warp per node) -------------------------
template<int D, bool P>
__device__ void gat_body(int lb, const int* __restrict__ rp, const int* __restrict__ srcS,
                         const float* __restrict__ wS,
                         const float* __restrict__ xl, const float* __restrict__ xr,
                         const float* __restrict__ att,
                         const float* __restrict__ bias, float* __restrict__ out,
                         const int* __restrict__ pidx) {
    constexpr int T = D / 128;
    int node = (lb * 256 + threadIdx.x) >> 5;
    int lane = threadIdx.x & 31;
    if (node >= NN) return;
    int beg = rp[node], end = rp[node + 1];
    int nr = P ? pidx[node] : node;
    const float4* xrp = (const float4*)(xr + nr * D);
    const float4* ap = (const float4*)att;
    float4 xrv[T], av[T], acc[T];
#pragma unroll
    for (int t = 0; t < T; t++) {
        xrv[t] = xrp[lane + t * 32];
        av[t] = ap[lane + t * 32];
        acc[t] = make_float4(0.f, 0.f, 0.f, 0.f);
    }
    float den = 0.f;
    for (int k = beg; k < end; k++) {
        int s = srcS[k];
        if (P) s = pidx[s];
        const float4* xp = (const float4*)(xl + s * D);
        float4 v[T];
        float lg = 0.f;
#pragma unroll
        for (int t = 0; t < T; t++) {
            v[t] = xp[lane + t * 32];
            float ex = v[t].x + xrv[t].x; ex = ex > 0.f ? ex : 0.2f * ex;
            float ey = v[t].y + xrv[t].y; ey = ey > 0.f ? ey : 0.2f * ey;
            float ez = v[t].z + xrv[t].z; ez = ez > 0.f ? ez : 0.2f * ez;
            float ew = v[t].w + xrv[t].w; ew = ew > 0.f ? ew : 0.2f * ew;
            lg += ex * av[t].x + ey * av[t].y + ez * av[t].z + ew * av[t].w;
        }
#pragma unroll
        for (int o = 16; o; o >>= 1) lg += __shfl_xor_sync(0xffffffffu, lg, o);
        float w = __expf(lg);
        den += w;
        float a = w * wS[k];
#pragma unroll
        for (int t = 0; t < T; t++) {
            acc[t].x += a * v[t].x; acc[t].y += a * v[t].y;
            acc[t].z += a * v[t].z; acc[t].w += a * v[t].w;
        }
    }
    float inv = 1.f / (den + 1e-16f);
    float4* op = (float4*)(out + node * D);
    const float4* bp = (const float4*)bias;
#pragma unroll
    for (int t = 0; t < T; t++) {
        float4 b = bp[lane + t * 32];
        op[lane + t * 32] = make_float4(acc[t].x * inv + b.x, acc[t].y * inv + b.y,
                                        acc[t].z * inv + b.z, acc[t].w * inv + b.w);
    }
}

// 3 encoder GATs in one kernel (homogeneous: no smem)
__global__ void __launch_bounds__(256) k_gat_enc(const float* att, const float* bias, float* hi) {
    int b = blockIdx.x;
    int y = b >> 10, lb = b & 1023;
    if (y == 0) gat_body<DL, false>(lb, g_rp_s, g_src_s, g_w_s, g_xl_e, g_xr_e, att, bias, hi, nullptr);
    else if (y == 1) gat_body<DL, false>(lb, g_rp_f, g_src_f, g_w_f, g_xl_p, g_xr_p, att, bias, g_g1, nullptr);
    else gat_body<DL, true>(lb, g_rp_s, g_src_s, g_w_s, g_xl_e, g_xr_e, att, bias, g_g2, g_perm);
}

// ------------------------- BN apply + ELU + L2 + bf16 -------------------------
__device__ void bnl2_body(int lb, const float* __restrict__ a0, const float* __restrict__ a1,
                          const float* __restrict__ a2,
                          const float* __restrict__ gamma, const float* __restrict__ beta) {
    int y = lb / 1024, xb = lb % 1024;
    const float* A = (y == 0) ? a0 : (y == 1 ? a1 : a2);
    __nv_bfloat16* B = (y == 0) ? g_q16 : (y == 1 ? g_p16 : g_n16);
    int gt = xb * 256 + threadIdx.x;
    int row = gt >> 5, lane = threadIdx.x & 31;
    if (row >= NN) return;
    float4 v = ((const float4*)(A + row * DL))[lane];
    float4 sm = ((const float4*)g_bns[y])[lane];
    float4 sq = ((const float4*)g_bnq[y])[lane];
    float4 ga = ((const float4*)gamma)[lane];
    float4 be = ((const float4*)beta)[lane];
    float mu, var, t;
#define BNE(comp) \
    mu = sm.comp * (1.f / NN); var = sq.comp * (1.f / NN) - mu * mu; \
    t = (v.comp - mu) * rsqrtf(var + 1e-5f) * ga.comp + be.comp; \
    v.comp = t > 0.f ? t : expm1f(t);
    BNE(x) BNE(y) BNE(z) BNE(w)
#undef BNE
    float s = v.x * v.x + v.y * v.y + v.z * v.z + v.w * v.w;
#pragma unroll
    for (int o = 16; o; o >>= 1) s += __shfl_xor_sync(0xffffffffu, s, o);
    float inv = 1.f / sqrtf(s);
    __nv_bfloat162* qp = (__nv_bfloat162*)(B + row * DL);
    qp[lane * 2]     = __floats2bfloat162_rn(v.x * inv, v.y * inv);
    qp[lane * 2 + 1] = __floats2bfloat162_rn(v.z * inv, v.w * inv);
}

// k_post: gat_dec(1024) | bnl2(3072)  (both smem-free)
__global__ void __launch_bounds__(256) k_post(const float* dec_att, const float* dec_b, float* h,
                                              const float* hiOut, const float* bn_g, const float* bn_b) {
    int b = blockIdx.x;
    if (b < 1024) gat_body<DI, false>(b, g_rp_s, g_src_s, g_w_s, g_xl_d, g_xr_d, dec_att, dec_b, h, nullptr);
    else bnl2_body(b - 1024, hiOut, g_g1, g_g2, bn_g, bn_b);
}

// ------------------------- InfoNCE on tensor cores (bf16 wmma) -------------------------
#define NCE_SMEM (64*128*2 + 128*128*2 + 8*16*68*4)
__global__ void k_nce() {
    extern __shared__ char smraw[];
    __nv_bfloat16* qs = (__nv_bfloat16*)smraw;            // [64][128]
    __nv_bfloat16* ns = qs + 64 * 128;                    // [128][128]
    float* stb = (float*)(ns + 128 * 128);                // 8 warps x [16][68]
    __shared__ float pos2[64];
    __shared__ float rowS[64];
    __shared__ float blksum;
    int tid = threadIdx.x;
    int warp = tid >> 5, lane = tid & 31;
    int r0 = blockIdx.x * 64;

    {
        const uint4* src = (const uint4*)(g_q16 + r0 * DL);
        uint4* dst4 = (uint4*)qs;
#pragma unroll
        for (int i = tid; i < 64 * 128 / 8; i += 256) dst4[i] = src[i];
    }
    if (tid < 64) rowS[tid] = 0.f;
    if (tid == 0) blksum = 0.f;
    __syncthreads();

    {
        int row = tid >> 2, part = tid & 3;
        float s = 0.f;
        const __nv_bfloat16* pr = g_p16 + (r0 + row) * DL;
        for (int k = part * 32; k < part * 32 + 32; k++)
            s += __bfloat162float(qs[row * 128 + k]) * __bfloat162float(pr[k]);
        s += __shfl_down_sync(0xffffffffu, s, 1);
        s += __shfl_down_sync(0xffffffffu, s, 2);
        if (part == 0) pos2[row] = 2.f * s;
    }

    int wm = (warp & 3) * 16;
    int wn = (warp >> 2) * 64;
    float* myst = stb + warp * (16 * 68);
    int lrow = lane >> 1;
    int lcol0 = (lane & 1) * 32;
    float sacc = 0.f;

    wmma::fragment<wmma::accumulator, 16, 16, 16, float> c[4];
    for (int n0 = 0; n0 < NN; n0 += 128) {
        __syncthreads();
        {
            const uint4* src = (const uint4*)(g_n16 + n0 * DL);
            uint4* dst4 = (uint4*)ns;
#pragma unroll
            for (int i = tid; i < 128 * 128 / 8; i += 256) dst4[i] = src[i];
        }
        __syncthreads();
#pragma unroll
        for (int j = 0; j < 4; j++) wmma::fill_fragment(c[j], 0.f);
#pragma unroll
        for (int k0 = 0; k0 < 8; k0++) {
            wmma::fragment<wmma::matrix_a, 16, 16, 16, __nv_bfloat16, wmma::row_major> a;
            wmma::load_matrix_sync(a, qs + wm * 128 + k0 * 16, 128);
#pragma unroll
            for (int j = 0; j < 4; j++) {
                wmma::fragment<wmma::matrix_b, 16, 16, 16, __nv_bfloat16, wmma::col_major> b;
                wmma::load_matrix_sync(b, ns + (wn + j * 16) * 128 + k0 * 16, 128);
                wmma::mma_sync(c[j], a, b, c[j]);
            }
        }
#pragma unroll
        for (int j = 0; j < 4; j++)
            wmma::store_matrix_sync(myst + j * 16, c[j], 68, wmma::mem_row_major);
        __syncwarp();
#pragma unroll
        for (int cc = 0; cc < 32; cc++) {
            float v = myst[lrow * 68 + lcol0 + cc];
            sacc += __expf(2.f * v);
        }
        __syncwarp();
    }
    sacc += __shfl_xor_sync(0xffffffffu, sacc, 1);
    if ((lane & 1) == 0) atomicAdd(&rowS[wm + lrow], sacc);
    __syncthreads();
    if (tid < 64) {
        float S = rowS[tid];
        float p = pos2[tid];
        float l = logf(S + __expf(p)) - p;
        atomicAdd(&blksum, l);
    }
    __syncthreads();
    if (tid == 0) atomicAdd(&g_acc[1], blksum);
}

// ------------------------- rec loss + self-finalizing last block -------------------------
__global__ void __launch_bounds__(256) k_rec(const float* __restrict__ x, const float* __restrict__ h,
                                             float* __restrict__ loss) {
    float s = 0.f;
    for (int i = blockIdx.x * blockDim.x + threadIdx.x; i < NN * DI; i += gridDim.x * blockDim.x) {
        float d = x[i] - h[i];
        s += d * d;
    }
#pragma unroll
    for (int o = 16; o; o >>= 1) s += __shfl_down_sync(0xffffffffu, s, o);
    __shared__ float red[8];
    int lane = threadIdx.x & 31, wid = threadIdx.x >> 5;
    if (lane == 0) red[wid] = s;
    __syncthreads();
    if (threadIdx.x == 0) {
        float t = 0.f;
        for (int i = 0; i < 8; i++) t += red[i];
        atomicAdd(&g_acc[0], t);
        __threadfence();
        unsigned old = atomicInc(&g_cnt, 255u);   // wraps to 0 on last block
        if (old == 255u) {
            __threadfence();
            loss[0] = g_acc[0] * (1.f / (float)(NN * DI)) + 0.2f * (g_acc[1] * (1.f / (float)NN));
        }
    }
}

// ------------------------- host orchestration -------------------------
extern "C" void kernel_launch(void* const* d_in, const int* in_sizes, int n_in,
                              void* d_out, int out_size) {
    (void)in_sizes; (void)n_in; (void)out_size;
    const float* x       = (const float*)d_in[0];
    const int*   gsi     = (const int*)d_in[1];
    const int*   gfi     = (const int*)d_in[2];
    const float* w_h     = (const float*)d_in[3];
    const float* w_h_a   = (const float*)d_in[4];
    const float* enc_Wl  = (const float*)d_in[5];
    const float* enc_Wr  = (const float*)d_in[6];
    const float* enc_att = (const float*)d_in[7];
    const float* enc_b   = (const float*)d_in[8];
    const float* dec_Wl  = (const float*)d_in[9];
    const float* dec_Wr  = (const float*)d_in[10];
    const float* dec_att = (const float*)d_in[11];
    const float* dec_b   = (const float*)d_in[12];
    const float* bn_g    = (const float*)d_in[13];
    const float* bn_b    = (const float*)d_in[14];

    float* out  = (float*)d_out;
    float* hi   = out;
    float* h    = out + H_OFF;
    float* loss = out + LOSS_OFF;

    const int* s_src = gsi;
    const int* s_dst = gsi + EE;
    const int* f_src = gfi;
    const int* f_dst = gfi + EE;

    float* xl_e = nullptr; (void)xl_e;

    cudaFuncSetAttribute(k_nce, cudaFuncAttributeMaxDynamicSharedMemorySize, NCE_SMEM);

    // device-symbol pointers
    void* p;
    cudaGetSymbolAddress(&p, g_Ah); __nv_bfloat16* Ah = (__nv_bfloat16*)p;
    cudaGetSymbolAddress(&p, g_Al); __nv_bfloat16* Al = (__nv_bfloat16*)p;
    cudaGetSymbolAddress(&p, g_xl_e); float* xle = (float*)p;
    cudaGetSymbolAddress(&p, g_xr_e); float* xre = (float*)p;
    cudaGetSymbolAddress(&p, g_xl_p); float* xlp = (float*)p;
    cudaGetSymbolAddress(&p, g_xr_p); float* xrp = (float*)p;
    cudaGetSymbolAddress(&p, g_xl_d); float* xld = (float*)p;
    cudaGetSymbolAddress(&p, g_xr_d); float* xrd = (float*)p;
    cudaGetSymbolAddress(&p, g_g1); float* gg1 = (float*)p;
    cudaGetSymbolAddress(&p, g_g2); float* gg2 = (float*)p;

    k_init<<<32, 256>>>();
    k_bits2<<<32, 256>>>();
    k_rankA<<<1024, 256>>>();
    k_rankB<<<1024, 256>>>();
    k_hist2<<<2048, 256>>>(s_dst, f_dst);
    k_scan2<<<2, 1024>>>();
    k_fill2<<<2048, 256>>>(s_src, s_dst, w_h, f_src, f_dst, w_h_a);

    kCP_enc<<<2560, 256>>>(x, enc_Wl, enc_Wr);
    k_gemm3<<<512, 256>>>(Ah, Al, DI, xle, xre, xlp, xrp, 7);
    k_gat_enc<<<3072, 256>>>(enc_att, enc_b, hi);

    kCP_dec<<<1376, 256>>>(hi, dec_Wl, dec_Wr, gg1, gg2);
    k_gemm3<<<512, 256>>>(Ah, Al, DL, xld, xrd, xld, xrd, 8);
    k_post<<<4096, 256>>>(dec_att, dec_b, h, hi, bn_g, bn_b);

    k_nce<<<128, 256, NCE_SMEM>>>();
    k_rec<<<256, 256>>>(x, h, loss);
}

// round 8
// speedup vs baseline: 1.4356x; 1.0050x over previous
#include <cuda_runtime.h>
#include <cuda_bf16.h>
#include <mma.h>
#include <stdint.h>
#include <math.h>

using namespace nvcuda;

#define NN 8192
#define EE 262144
#define DI 256
#define DL 128

#define H_OFF (NN*DL)
#define LOSS_OFF (NN*DL + NN*DI)

// ------------------------- scratch (__device__ globals; zero-initialized) -------------------------
__device__ float g_xl_e[NN*DL];
__device__ float g_xr_e[NN*DL];
__device__ float g_xl_p[NN*DL];
__device__ float g_xr_p[NN*DL];
__device__ float g_xl_d[NN*DI];
__device__ float g_xr_d[NN*DI];
__device__ float g_g1[NN*DL];
__device__ float g_g2[NN*DL];
__device__ __nv_bfloat16 g_q16[NN*DL];
__device__ __nv_bfloat16 g_p16[NN*DL];
__device__ __nv_bfloat16 g_n16[NN*DL];
__device__ int g_perm[NN];
__device__ unsigned g_bits0[NN];
__device__ unsigned g_bits1[NN];
__device__ float g_bns[3][DL];
__device__ float g_bnq[3][DL];
__device__ float g_acc[2];         // [0]=rec_sum [1]=ctr_sum
__device__ unsigned g_cnt;

// bucket-sort rank scratch
__device__ int g_bh0[NN];
__device__ int g_bh1[NN];
__device__ int g_bs0[NN+1];
__device__ int g_bs1[NN+1];
__device__ int g_bc0[NN];
__device__ int g_bc1[NN];
__device__ int g_si0[NN];
__device__ int g_si1[NN];
__device__ int g_r0[NN];
__device__ int g_r1[NN];

// bf16 split buffers
__device__ __nv_bfloat16 g_Ah[NN*DI];
__device__ __nv_bfloat16 g_Al[NN*DI];
__device__ __nv_bfloat16 g_Bh[DI*512];
__device__ __nv_bfloat16 g_Bl[DI*512];

// CSR scratch (per graph)
__device__ int g_deg_s[NN];
__device__ int g_deg_f[NN];
__device__ int g_cur_s[NN];
__device__ int g_cur_f[NN];
__device__ int g_rp_s[NN+1];
__device__ int g_src_s[EE];
__device__ float g_w_s[EE];
__device__ int g_rp_f[NN+1];
__device__ int g_src_f[EE];
__device__ float g_w_f[EE];

// ------------------------- threefry2x32-20 -------------------------
__device__ __forceinline__ void tfry(uint32_t k0, uint32_t k1, uint32_t x0, uint32_t x1,
                                     uint32_t* o0, uint32_t* o1) {
    uint32_t ks2 = k0 ^ k1 ^ 0x1BD11BDAu;
    x0 += k0; x1 += k1;
#define RR(r) { x0 += x1; x1 = (x1 << (r)) | (x1 >> (32 - (r))); x1 ^= x0; }
    RR(13) RR(15) RR(26) RR(6)  x0 += k1;  x1 += ks2 + 1u;
    RR(17) RR(29) RR(16) RR(24) x0 += ks2; x1 += k0 + 2u;
    RR(13) RR(15) RR(26) RR(6)  x0 += k0;  x1 += k1 + 3u;
    RR(17) RR(29) RR(16) RR(24) x0 += k1;  x1 += ks2 + 4u;
    RR(13) RR(15) RR(26) RR(6)  x0 += ks2; x1 += k0 + 5u;
#undef RR
    *o0 = x0; *o1 = x1;
}

// keys[0:2]=sub1, [2:4]=sub2, [4:6]=k2  (pure function of key(42))
__device__ __forceinline__ void all_keys(uint32_t* ks) {
    uint32_t a0, a1, b0, b1;
    tfry(0u, 42u, 0u, 2u, &a0, &a1);
    tfry(0u, 42u, 1u, 3u, &b0, &b1);
    uint32_t c0, c1, d0, d1;
    tfry(a0, b0, 0u, 2u, &c0, &c1);
    tfry(a0, b0, 1u, 3u, &d0, &d1);
    ks[0] = c1; ks[1] = d1;
    uint32_t e0, e1, f0, f1;
    tfry(c0, d0, 0u, 2u, &e0, &e1);
    tfry(c0, d0, 1u, 3u, &f0, &f1);
    ks[2] = e1; ks[3] = f1;
    ks[4] = a1; ks[5] = b1;
}

// ------------------------- init: zero deg/hist/bn/acc -------------------------
__global__ void __launch_bounds__(256) k_init() {
    int t = blockIdx.x * 256 + threadIdx.x;
    if (t < NN) {
        g_deg_s[t] = 0; g_deg_f[t] = 0;
        g_bh0[t] = 0; g_bh1[t] = 0;
    }
    if (t < DL) {
        g_bns[0][t] = 0.f; g_bns[1][t] = 0.f; g_bns[2][t] = 0.f;
        g_bnq[0][t] = 0.f; g_bnq[1][t] = 0.f; g_bnq[2][t] = 0.f;
    }
    if (t == 0) { g_acc[0] = 0.f; g_acc[1] = 0.f; }
}

// ------------------------- RNG bits + bucket histogram -------------------------
__global__ void __launch_bounds__(256) k_bits2() {
    int b = blockIdx.x;
    int which = (b < 16) ? 0 : 1;
    int i = (which ? b - 16 : b) * 256 + threadIdx.x;
    if (i >= NN / 2) return;
    uint32_t ks[6];
    all_keys(ks);
    uint32_t lo, hi;
    tfry(ks[which * 2], ks[which * 2 + 1], (uint32_t)i, (uint32_t)(i + NN / 2), &lo, &hi);
    unsigned* bits = which ? g_bits1 : g_bits0;
    int* bh = which ? g_bh1 : g_bh0;
    bits[i] = lo; bits[i + NN / 2] = hi;
    atomicAdd(&bh[lo >> 19], 1);
    atomicAdd(&bh[hi >> 19], 1);
}

// ------------------------- CSR build -------------------------
__global__ void __launch_bounds__(256) k_hist2(const int* __restrict__ s_dst,
                                               const int* __restrict__ f_dst) {
    int b = blockIdx.x;
    if (b < 1024) {
        int e = b * 256 + threadIdx.x;
        if (e < EE) atomicAdd(&g_deg_s[s_dst[e]], 1);
    } else {
        int e = (b - 1024) * 256 + threadIdx.x;
        if (e < EE) atomicAdd(&g_deg_f[f_dst[e]], 1);
    }
}

__device__ void scan_body(const int* __restrict__ deg, int* __restrict__ rp, int* __restrict__ cur) {
    __shared__ int wsum[32];
    int tid = threadIdx.x;
    int lane = tid & 31, w = tid >> 5;
    int loc[8]; int s = 0;
#pragma unroll
    for (int i = 0; i < 8; i++) { loc[i] = deg[tid * 8 + i]; s += loc[i]; }
    int ss = s;
#pragma unroll
    for (int o = 1; o < 32; o <<= 1) { int v = __shfl_up_sync(0xffffffffu, ss, o); if (lane >= o) ss += v; }
    if (lane == 31) wsum[w] = ss;
    __syncthreads();
    if (w == 0) {
        int v = wsum[lane];
#pragma unroll
        for (int o = 1; o < 32; o <<= 1) { int u = __shfl_up_sync(0xffffffffu, v, o); if (lane >= o) v += u; }
        wsum[lane] = v;
    }
    __syncthreads();
    int base = ss - s + (w > 0 ? wsum[w - 1] : 0);
#pragma unroll
    for (int i = 0; i < 8; i++) { rp[tid * 8 + i] = base; cur[tid * 8 + i] = base; base += loc[i]; }
    if (tid == 1023) rp[NN] = base;
}

__global__ void __launch_bounds__(1024) k_scan4() {
    int b = blockIdx.x;
    if (b == 0) scan_body(g_deg_s, g_rp_s, g_cur_s);
    else if (b == 1) scan_body(g_deg_f, g_rp_f, g_cur_f);
    else if (b == 2) scan_body(g_bh0, g_bs0, g_bc0);
    else scan_body(g_bh1, g_bs1, g_bc1);
}

// edge fill (2048 blocks) + bucket scatter (64 blocks)
__global__ void __launch_bounds__(256) k_fill2(const int* __restrict__ s_src, const int* __restrict__ s_dst,
                                               const float* __restrict__ w_h,
                                               const int* __restrict__ f_src, const int* __restrict__ f_dst,
                                               const float* __restrict__ w_h_a) {
    int b = blockIdx.x;
    if (b < 1024) {
        int e = b * 256 + threadIdx.x;
        if (e >= EE) return;
        int d = s_dst[e];
        int pos = atomicAdd(&g_cur_s[d], 1);
        g_src_s[pos] = s_src[e];
        g_w_s[pos] = w_h[e];
    } else if (b < 2048) {
        int e = (b - 1024) * 256 + threadIdx.x;
        if (e >= EE) return;
        int d = f_dst[e];
        int pos = atomicAdd(&g_cur_f[d], 1);
        g_src_f[pos] = f_src[e];
        g_w_f[pos] = w_h_a[e];
    } else if (b < 2080) {
        int i = (b - 2048) * 256 + threadIdx.x;
        if (i >= NN) return;
        int pos = atomicAdd(&g_bc0[g_bits0[i] >> 19], 1);
        g_si0[pos] = i;
    } else {
        int i = (b - 2080) * 256 + threadIdx.x;
        if (i >= NN) return;
        int pos = atomicAdd(&g_bc1[g_bits1[i] >> 19], 1);
        g_si1[pos] = i;
    }
}

// per-element rank via bucket scan (both keys, independent)
__global__ void __launch_bounds__(256) k_rank() {
    int b = blockIdx.x;
    int which = (b < 32) ? 0 : 1;
    int p = (which ? b - 32 : b) * 256 + threadIdx.x;
    if (p >= NN) return;
    const unsigned* bits = which ? g_bits1 : g_bits0;
    const int* si = which ? g_si1 : g_si0;
    const int* bs = which ? g_bs1 : g_bs0;
    int* r = which ? g_r1 : g_r0;
    int i = si[p];
    unsigned bi = bits[i];
    unsigned long long ki = (((unsigned long long)bi) << 13) | (unsigned)i;
    int bkt = bi >> 19;
    int beg = bs[bkt], end = bs[bkt + 1];
    int cnt = 0;
    for (int q = beg; q < end; q++) {
        int j = si[q];
        unsigned long long kj = (((unsigned long long)bits[j]) << 13) | (unsigned)j;
        cnt += (kj < ki);
    }
    r[i] = beg + cnt;
}

// ------------------------- cvt / pack bodies -------------------------
__device__ void cvt4_body(int lb, const float* __restrict__ src,
                          __nv_bfloat16* __restrict__ hi, __nv_bfloat16* __restrict__ lo, int n4) {
    int i = lb * 256 + threadIdx.x;
    if (i >= n4) return;
    float4 a = ((const float4*)src)[i];
    __nv_bfloat162 h0 = __floats2bfloat162_rn(a.x, a.y);
    __nv_bfloat162 h1 = __floats2bfloat162_rn(a.z, a.w);
    float lx = a.x - __bfloat162float(__low2bfloat16(h0));
    float ly = a.y - __bfloat162float(__high2bfloat16(h0));
    float lz = a.z - __bfloat162float(__low2bfloat16(h1));
    float lw = a.w - __bfloat162float(__high2bfloat16(h1));
    ((__nv_bfloat162*)hi)[i * 2] = h0;
    ((__nv_bfloat162*)hi)[i * 2 + 1] = h1;
    ((__nv_bfloat162*)lo)[i * 2] = __floats2bfloat162_rn(lx, ly);
    ((__nv_bfloat162*)lo)[i * 2 + 1] = __floats2bfloat162_rn(lz, lw);
}

__device__ __forceinline__ float keep_val(int k) {
    uint32_t ks[6];
    all_keys(ks);
    uint32_t lo, hi;
    int i = (k < 128) ? k : (k - 128);
    tfry(ks[4], ks[5], (uint32_t)i, (uint32_t)(i + 128), &lo, &hi);
    uint32_t u = (k < 128) ? lo : hi;
    float uf = __uint_as_float((u >> 9) | 0x3f800000u) - 1.0f;
    return (uf >= 0.3f) ? 1.f : 0.f;
}

// kCP_enc: cvt_enc(2048) | packB_enc(512) | perm combine(32)
__global__ void __launch_bounds__(256) kCP_enc(const float* __restrict__ x,
                                               const float* __restrict__ Wl, const float* __restrict__ Wr) {
    int b = blockIdx.x;
    if (b < 2048) { cvt4_body(b, x, g_Ah, g_Al, NN * DI / 4); return; }
    if (b < 2560) {
        int idx = (b - 2048) * 256 + threadIdx.x;
        if (idx >= DI * 512) return;
        int k = idx >> 9, c = idx & 511;
        float v;
        if (c < 128) v = Wl[k * 128 + c];
        else if (c < 256) v = Wr[k * 128 + c - 128];
        else if (c < 384) v = keep_val(k) * Wl[k * 128 + c - 256];
        else v = keep_val(k) * Wr[k * 128 + c - 384];
        __nv_bfloat16 h = __float2bfloat16_rn(v);
        g_Bh[idx] = h;
        g_Bl[idx] = __float2bfloat16_rn(v - __bfloat162float(h));
        return;
    }
    // perm combine: perm[r1[r0[j]]] = j
    int j = (b - 2560) * 256 + threadIdx.x;
    if (j < NN) g_perm[g_r1[g_r0[j]]] = j;
}

// bnstats body
__device__ void bnstats_body(int lb, const float* __restrict__ a0, const float* __restrict__ a1,
                             const float* __restrict__ a2) {
    int y = lb / 32, xb = lb % 32;
    const float* A = (y == 0) ? a0 : (y == 1 ? a1 : a2);
    int c = threadIdx.x % DL;
    int part = threadIdx.x / DL;
    int rbase = xb * 256 + part * 128;
    float s = 0.f, q = 0.f;
    for (int r = 0; r < 128; r++) {
        float v = A[(rbase + r) * DL + c];
        s += v; q += v * v;
    }
    atomicAdd(&g_bns[y][c], s);
    atomicAdd(&g_bnq[y][c], q);
}

// kCP_dec: cvt_dec(1024) | packB_dec(256) | bnstats(96)
__global__ void __launch_bounds__(256) kCP_dec(const float* __restrict__ hiOut,
                                               const float* __restrict__ Wl, const float* __restrict__ Wr,
                                               const float* __restrict__ g1, const float* __restrict__ g2) {
    int b = blockIdx.x;
    if (b < 1024) { cvt4_body(b, hiOut, g_Ah, g_Al, NN * DL / 4); return; }
    if (b < 1280) {
        int idx = (b - 1024) * 256 + threadIdx.x;
        if (idx >= DL * 512) return;
        int k = idx >> 9, c = idx & 511;
        float v = (c < 256) ? Wl[k * 256 + c] : Wr[k * 256 + c - 256];
        __nv_bfloat16 h = __float2bfloat16_rn(v);
        g_Bh[idx] = h;
        g_Bl[idx] = __float2bfloat16_rn(v - __bfloat162float(h));
        return;
    }
    bnstats_body(b - 1280, hiOut, g1, g2);
}

// ------------------------- bf16x3 GEMM on tensor cores -------------------------
__global__ void __launch_bounds__(256) k_gemm3(const __nv_bfloat16* __restrict__ Ah,
                                               const __nv_bfloat16* __restrict__ Al, int K,
                                               float* o0, float* o1, float* o2, float* o3, int lgw) {
    __shared__ __nv_bfloat16 sAh[64 * 40], sAl[64 * 40];
    __shared__ __nv_bfloat16 sBh[32 * 136], sBl[32 * 136];
    int tid = threadIdx.x;
    int warp = tid >> 5;
    int wm = warp >> 2, wn = warp & 3;
    int bx = blockIdx.x;
    int row0 = (bx >> 2) * 64, col0 = (bx & 3) * 128;
    wmma::fragment<wmma::accumulator, 16, 16, 16, float> c[2][2];
#pragma unroll
    for (int i = 0; i < 2; i++)
#pragma unroll
        for (int j = 0; j < 2; j++) wmma::fill_fragment(c[i][j], 0.f);
    int r = tid >> 2, q = tid & 3;
    for (int kp = 0; kp < K; kp += 32) {
        __syncthreads();
        *(uint4*)&sAh[r * 40 + q * 8] = *(const uint4*)&Ah[(row0 + r) * K + kp + q * 8];
        *(uint4*)&sAl[r * 40 + q * 8] = *(const uint4*)&Al[(row0 + r) * K + kp + q * 8];
#pragma unroll
        for (int v = 0; v < 2; v++) {
            int idx = tid + v * 256;
            int k = idx >> 4, nq = idx & 15;
            *(uint4*)&sBh[k * 136 + nq * 8] = *(const uint4*)&g_Bh[(kp + k) * 512 + col0 + nq * 8];
            *(uint4*)&sBl[k * 136 + nq * 8] = *(const uint4*)&g_Bl[(kp + k) * 512 + col0 + nq * 8];
        }
        __syncthreads();
#pragma unroll
        for (int ks = 0; ks < 32; ks += 16) {
            wmma::fragment<wmma::matrix_a, 16, 16, 16, __nv_bfloat16, wmma::row_major> ah[2], al[2];
            wmma::fragment<wmma::matrix_b, 16, 16, 16, __nv_bfloat16, wmma::row_major> bh[2], bl[2];
#pragma unroll
            for (int i = 0; i < 2; i++) {
                wmma::load_matrix_sync(ah[i], &sAh[(wm * 32 + i * 16) * 40 + ks], 40);
                wmma::load_matrix_sync(al[i], &sAl[(wm * 32 + i * 16) * 40 + ks], 40);
            }
#pragma unroll
            for (int j = 0; j < 2; j++) {
                wmma::load_matrix_sync(bh[j], &sBh[ks * 136 + wn * 32 + j * 16], 136);
                wmma::load_matrix_sync(bl[j], &sBl[ks * 136 + wn * 32 + j * 16], 136);
            }
#pragma unroll
            for (int i = 0; i < 2; i++)
#pragma unroll
                for (int j = 0; j < 2; j++) {
                    wmma::mma_sync(c[i][j], ah[i], bh[j], c[i][j]);
                    wmma::mma_sync(c[i][j], ah[i], bl[j], c[i][j]);
                    wmma::mma_sync(c[i][j], al[i], bh[j], c[i][j]);
                }
        }
    }
    float* ob[4] = {o0, o1, o2, o3};
    int W = 1 << lgw, msk = W - 1;
#pragma unroll
    for (int i = 0; i < 2; i++)
#pragma unroll
        for (int j = 0; j < 2; j++) {
            int colg = col0 + wn * 32 + j * 16;
            float* dst = ob[colg >> lgw] + (size_t)(row0 + wm * 32 + i * 16) * W + (colg & msk);
            wmma::store_matrix_sync(dst, c[i][j], W, wmma::mem_row_major);
        }
}

// ------------------------- fused single-pass GAT (warp per node) -------------------------
template<int D, bool P>
__device__ void gat_body(int lb, const int* __restrict__ rp, const int* __restrict__ srcS,
                         const float* __restrict__ wS,
                         const float* __restrict__ xl, const float* __restrict__ xr,
                         const float* __restrict__ att,
                         const float* __restrict__ bias, float* __restrict__ out,
                         const int* __restrict__ pidx) {
    constexpr int T = D / 128;
    int node = (lb * 256 + threadIdx.x) >> 5;
    int lane = threadIdx.x & 31;
    if (node >= NN) return;
    int beg = rp[node], end = rp[node + 1];
    int nr = P ? pidx[node] : node;
    const float4* xrp = (const float4*)(xr + nr * D);
    const float4* ap = (const float4*)att;
    float4 xrv[T], av[T], acc[T];
#pragma unroll
    for (int t = 0; t < T; t++) {
        xrv[t] = xrp[lane + t * 32];
        av[t] = ap[lane + t * 32];
        acc[t] = make_float4(0.f, 0.f, 0.f, 0.f);
    }
    float den = 0.f;
    for (int k = beg; k < end; k++) {
        int s = srcS[k];
        if (P) s = pidx[s];
        const float4* xp = (const float4*)(xl + s * D);
        float4 v[T];
        float lg = 0.f;
#pragma unroll
        for (int t = 0; t < T; t++) {
            v[t] = xp[lane + t * 32];
            float ex = v[t].x + xrv[t].x; ex = ex > 0.f ? ex : 0.2f * ex;
            float ey = v[t].y + xrv[t].y; ey = ey > 0.f ? ey : 0.2f * ey;
            float ez = v[t].z + xrv[t].z; ez = ez > 0.f ? ez : 0.2f * ez;
            float ew = v[t].w + xrv[t].w; ew = ew > 0.f ? ew : 0.2f * ew;
            lg += ex * av[t].x + ey * av[t].y + ez * av[t].z + ew * av[t].w;
        }
#pragma unroll
        for (int o = 16; o; o >>= 1) lg += __shfl_xor_sync(0xffffffffu, lg, o);
        float w = __expf(lg);
        den += w;
        float a = w * wS[k];
#pragma unroll
        for (int t = 0; t < T; t++) {
            acc[t].x += a * v[t].x; acc[t].y += a * v[t].y;
            acc[t].z += a * v[t].z; acc[t].w += a * v[t].w;
        }
    }
    float inv = 1.f / (den + 1e-16f);
    float4* op = (float4*)(out + node * D);
    const float4* bp = (const float4*)bias;
#pragma unroll
    for (int t = 0; t < T; t++) {
        float4 b = bp[lane + t * 32];
        op[lane + t * 32] = make_float4(acc[t].x * inv + b.x, acc[t].y * inv + b.y,
                                        acc[t].z * inv + b.z, acc[t].w * inv + b.w);
    }
}

// 3 encoder GATs in one kernel (homogeneous: no smem)
__global__ void __launch_bounds__(256) k_gat_enc(const float* att, const float* bias, float* hi) {
    int b = blockIdx.x;
    int y = b >> 10, lb = b & 1023;
    if (y == 0) gat_body<DL, false>(lb, g_rp_s, g_src_s, g_w_s, g_xl_e, g_xr_e, att, bias, hi, nullptr);
    else if (y == 1) gat_body<DL, false>(lb, g_rp_f, g_src_f, g_w_f, g_xl_p, g_xr_p, att, bias, g_g1, nullptr);
    else gat_body<DL, true>(lb, g_rp_s, g_src_s, g_w_s, g_xl_e, g_xr_e, att, bias, g_g2, g_perm);
}

// ------------------------- BN apply + ELU + L2 + bf16 -------------------------
__device__ void bnl2_body(int lb, const float* __restrict__ a0, const float* __restrict__ a1,
                          const float* __restrict__ a2,
                          const float* __restrict__ gamma, const float* __restrict__ beta) {
    int y = lb / 1024, xb = lb % 1024;
    const float* A = (y == 0) ? a0 : (y == 1 ? a1 : a2);
    __nv_bfloat16* B = (y == 0) ? g_q16 : (y == 1 ? g_p16 : g_n16);
    int gt = xb * 256 + threadIdx.x;
    int row = gt >> 5, lane = threadIdx.x & 31;
    if (row >= NN) return;
    float4 v = ((const float4*)(A + row * DL))[lane];
    float4 sm = ((const float4*)g_bns[y])[lane];
    float4 sq = ((const float4*)g_bnq[y])[lane];
    float4 ga = ((const float4*)gamma)[lane];
    float4 be = ((const float4*)beta)[lane];
    float mu, var, t;
#define BNE(comp) \
    mu = sm.comp * (1.f / NN); var = sq.comp * (1.f / NN) - mu * mu; \
    t = (v.comp - mu) * rsqrtf(var + 1e-5f) * ga.comp + be.comp; \
    v.comp = t > 0.f ? t : expm1f(t);
    BNE(x) BNE(y) BNE(z) BNE(w)
#undef BNE
    float s = v.x * v.x + v.y * v.y + v.z * v.z + v.w * v.w;
#pragma unroll
    for (int o = 16; o; o >>= 1) s += __shfl_xor_sync(0xffffffffu, s, o);
    float inv = 1.f / sqrtf(s);
    __nv_bfloat162* qp = (__nv_bfloat162*)(B + row * DL);
    qp[lane * 2]     = __floats2bfloat162_rn(v.x * inv, v.y * inv);
    qp[lane * 2 + 1] = __floats2bfloat162_rn(v.z * inv, v.w * inv);
}

// k_post: gat_dec(1024) | bnl2(3072)  (both smem-free)
__global__ void __launch_bounds__(256) k_post(const float* dec_att, const float* dec_b, float* h,
                                              const float* hiOut, const float* bn_g, const float* bn_b) {
    int b = blockIdx.x;
    if (b < 1024) gat_body<DI, false>(b, g_rp_s, g_src_s, g_w_s, g_xl_d, g_xr_d, dec_att, dec_b, h, nullptr);
    else bnl2_body(b - 1024, hiOut, g_g1, g_g2, bn_g, bn_b);
}

// ------------------------- InfoNCE on tensor cores (M=32 tiles, 256 blocks) -------------------------
#define NCE_SMEM (32*128*2 + 128*128*2 + 8*16*36*4)
__global__ void k_nce() {
    extern __shared__ char smraw[];
    __nv_bfloat16* qs = (__nv_bfloat16*)smraw;            // [32][128]
    __nv_bfloat16* ns = qs + 32 * 128;                    // [128][128]
    float* stb = (float*)(ns + 128 * 128);                // 8 warps x [16][36]
    __shared__ float pos2[32];
    __shared__ float rowS[32];
    __shared__ float blksum;
    int tid = threadIdx.x;
    int warp = tid >> 5, lane = tid & 31;
    int r0 = blockIdx.x * 32;

    {
        const uint4* src = (const uint4*)(g_q16 + r0 * DL);
        uint4* dst4 = (uint4*)qs;
#pragma unroll
        for (int i = tid; i < 32 * 128 / 8; i += 256) dst4[i] = src[i];
    }
    if (tid < 32) rowS[tid] = 0.f;
    if (tid == 0) blksum = 0.f;
    __syncthreads();

    {
        int row = tid >> 3, part = tid & 7;
        float s = 0.f;
        const __nv_bfloat16* pr = g_p16 + (r0 + row) * DL;
        for (int k = part * 16; k < part * 16 + 16; k++)
            s += __bfloat162float(qs[row * 128 + k]) * __bfloat162float(pr[k]);
        s += __shfl_down_sync(0xffffffffu, s, 1);
        s += __shfl_down_sync(0xffffffffu, s, 2);
        s += __shfl_down_sync(0xffffffffu, s, 4);
        if (part == 0) pos2[row] = 2.f * s;
    }

    int wm = (warp & 1) * 16;
    int wn = (warp >> 1) * 32;
    float* myst = stb + warp * (16 * 36);
    int lrow = lane >> 1;
    int lcol0 = (lane & 1) * 16;
    float sacc = 0.f;

    wmma::fragment<wmma::accumulator, 16, 16, 16, float> c[2];
    for (int n0 = 0; n0 < NN; n0 += 128) {
        __syncthreads();
        {
            const uint4* src = (const uint4*)(g_n16 + n0 * DL);
            uint4* dst4 = (uint4*)ns;
#pragma unroll
            for (int i = tid; i < 128 * 128 / 8; i += 256) dst4[i] = src[i];
        }
        __syncthreads();
#pragma unroll
        for (int j = 0; j < 2; j++) wmma::fill_fragment(c[j], 0.f);
#pragma unroll
        for (int k0 = 0; k0 < 8; k0++) {
            wmma::fragment<wmma::matrix_a, 16, 16, 16, __nv_bfloat16, wmma::row_major> a;
            wmma::load_matrix_sync(a, qs + wm * 128 + k0 * 16, 128);
#pragma unroll
            for (int j = 0; j < 2; j++) {
                wmma::fragment<wmma::matrix_b, 16, 16, 16, __nv_bfloat16, wmma::col_major> b;
                wmma::load_matrix_sync(b, ns + (wn + j * 16) * 128 + k0 * 16, 128);
                wmma::mma_sync(c[j], a, b, c[j]);
            }
        }
#pragma unroll
        for (int j = 0; j < 2; j++)
            wmma::store_matrix_sync(myst + j * 16, c[j], 36, wmma::mem_row_major);
        __syncwarp();
#pragma unroll
        for (int cc = 0; cc < 16; cc++) {
            float v = myst[lrow * 36 + lcol0 + cc];
            sacc += __expf(2.f * v);
        }
        __syncwarp();
    }
    sacc += __shfl_xor_sync(0xffffffffu, sacc, 1);
    if ((lane & 1) == 0) atomicAdd(&rowS[wm + lrow], sacc);
    __syncthreads();
    if (tid < 32) {
        float S = rowS[tid];
        float p = pos2[tid];
        float l = logf(S + __expf(p)) - p;
        atomicAdd(&blksum, l);
    }
    __syncthreads();
    if (tid == 0) atomicAdd(&g_acc[1], blksum);
}

// ------------------------- rec loss + self-finalizing last block -------------------------
__global__ void __launch_bounds__(256) k_rec(const float* __restrict__ x, const float* __restrict__ h,
                                             float* __restrict__ loss) {
    float s = 0.f;
    for (int i = blockIdx.x * blockDim.x + threadIdx.x; i < NN * DI; i += gridDim.x * blockDim.x) {
        float d = x[i] - h[i];
        s += d * d;
    }
#pragma unroll
    for (int o = 16; o; o >>= 1) s += __shfl_down_sync(0xffffffffu, s, o);
    __shared__ float red[8];
    int lane = threadIdx.x & 31, wid = threadIdx.x >> 5;
    if (lane == 0) red[wid] = s;
    __syncthreads();
    if (threadIdx.x == 0) {
        float t = 0.f;
        for (int i = 0; i < 8; i++) t += red[i];
        atomicAdd(&g_acc[0], t);
        __threadfence();
        unsigned old = atomicInc(&g_cnt, 255u);   // wraps to 0 on last block
        if (old == 255u) {
            __threadfence();
            loss[0] = g_acc[0] * (1.f / (float)(NN * DI)) + 0.2f * (g_acc[1] * (1.f / (float)NN));
        }
    }
}

// ------------------------- host orchestration -------------------------
extern "C" void kernel_launch(void* const* d_in, const int* in_sizes, int n_in,
                              void* d_out, int out_size) {
    (void)in_sizes; (void)n_in; (void)out_size;
    const float* x       = (const float*)d_in[0];
    const int*   gsi     = (const int*)d_in[1];
    const int*   gfi     = (const int*)d_in[2];
    const float* w_h     = (const float*)d_in[3];
    const float* w_h_a   = (const float*)d_in[4];
    const float* enc_Wl  = (const float*)d_in[5];
    const float* enc_Wr  = (const float*)d_in[6];
    const float* enc_att = (const float*)d_in[7];
    const float* enc_b   = (const float*)d_in[8];
    const float* dec_Wl  = (const float*)d_in[9];
    const float* dec_Wr  = (const float*)d_in[10];
    const float* dec_att = (const float*)d_in[11];
    const float* dec_b   = (const float*)d_in[12];
    const float* bn_g    = (const float*)d_in[13];
    const float* bn_b    = (const float*)d_in[14];

    float* out  = (float*)d_out;
    float* hi   = out;
    float* h    = out + H_OFF;
    float* loss = out + LOSS_OFF;

    const int* s_src = gsi;
    const int* s_dst = gsi + EE;
    const int* f_src = gfi;
    const int* f_dst = gfi + EE;

    cudaFuncSetAttribute(k_nce, cudaFuncAttributeMaxDynamicSharedMemorySize, NCE_SMEM);

    // device-symbol pointers
    void* p;
    cudaGetSymbolAddress(&p, g_Ah); __nv_bfloat16* Ah = (__nv_bfloat16*)p;
    cudaGetSymbolAddress(&p, g_Al); __nv_bfloat16* Al = (__nv_bfloat16*)p;
    cudaGetSymbolAddress(&p, g_xl_e); float* xle = (float*)p;
    cudaGetSymbolAddress(&p, g_xr_e); float* xre = (float*)p;
    cudaGetSymbolAddress(&p, g_xl_p); float* xlp = (float*)p;
    cudaGetSymbolAddress(&p, g_xr_p); float* xrp = (float*)p;
    cudaGetSymbolAddress(&p, g_xl_d); float* xld = (float*)p;
    cudaGetSymbolAddress(&p, g_xr_d); float* xrd = (float*)p;
    cudaGetSymbolAddress(&p, g_g1); float* gg1 = (float*)p;
    cudaGetSymbolAddress(&p, g_g2); float* gg2 = (float*)p;

    k_init<<<32, 256>>>();
    k_bits2<<<32, 256>>>();
    k_hist2<<<2048, 256>>>(s_dst, f_dst);
    k_scan4<<<4, 1024>>>();
    k_fill2<<<2112, 256>>>(s_src, s_dst, w_h, f_src, f_dst, w_h_a);
    k_rank<<<64, 256>>>();

    kCP_enc<<<2592, 256>>>(x, enc_Wl, enc_Wr);
    k_gemm3<<<512, 256>>>(Ah, Al, DI, xle, xre, xlp, xrp, 7);
    k_gat_enc<<<3072, 256>>>(enc_att, enc_b, hi);

    kCP_dec<<<1376, 256>>>(hi, dec_Wl, dec_Wr, gg1, gg2);
    k_gemm3<<<512, 256>>>(Ah, Al, DL, xld, xrd, xld, xrd, 8);
    k_post<<<4096, 256>>>(dec_att, dec_b, h, hi, bn_g, bn_b);

    k_nce<<<256, 256, NCE_SMEM>>>();
    k_rec<<<256, 256>>>(x, h, loss);
}